// round 14
// baseline (speedup 1.0000x reference)
#include <cuda_runtime.h>
#include <cuda_bf16.h>
#include <math.h>

// Problem constants (fixed by setup_inputs):
// B=16, nW=64, BnW=1024, N=64, C=256, H=8, d=32, rows R=65536
static const size_t SEG    = 16777216ull;
static const size_t O_QM   = 1ull * SEG;
static const size_t O_KM   = 2ull * SEG;
static const size_t O_VM   = 3ull * SEG;
static const size_t O_CELL = 4ull * SEG;
static const size_t O_AM   = 6ull * SEG;
static const size_t O_OM   = 7ull * SEG;

// ---------------- static device scratch (no allocations) ----------------
__device__ float          g_y[50331648];     // pre-BN q|k|v activations (65536 x 768)
__device__ float          g_yo[16777216];    // pre-BN o activations (65536 x 256)
__device__ __nv_bfloat16  g_a0[16777216];    // bf16 split planes of x (65536 x 256)
__device__ __nv_bfloat16  g_a1[16777216];
__device__ __nv_bfloat16  g_a2[16777216];
__device__ __nv_bfloat16  g_sp[16777216];    // attn-LIF spikes as bf16 (exact 0/1)
__device__ __nv_bfloat16  g_w0[262144];      // bf16 split planes of [Wq;Wk;Wv;Wo] (1024 x 256)
__device__ __nv_bfloat16  g_w1[262144];
__device__ __nv_bfloat16  g_w2[262144];
__device__ float          g_cs[524288];      // (BnW, N, H) coincidence state
__device__ float          g_bias[32768];     // (H, N, N) relative position bias
__device__ unsigned       g_qbits[524288];   // (BnW, H, N): packed spikes over d=32
__device__ unsigned       g_kbits[524288];
__device__ unsigned       g_vbits[524288];
__device__ float          g_pf[786432];      // stats partials: 512 rowblocks x (768 sum | 768 sumsq)
__device__ float          g_scale[768], g_shift[768];
__device__ float          g_scale_o[256], g_shift_o[256];

// ---------------- warp mma helpers (legacy path, plain sm_103) ----------------
__device__ __forceinline__ unsigned smem_u32(const void* p) {
    return (unsigned)__cvta_generic_to_shared(p);
}
__device__ __forceinline__ void ldsm_x4(unsigned r[4], unsigned saddr) {
    asm volatile("ldmatrix.sync.aligned.m8n8.x4.shared.b16 {%0,%1,%2,%3}, [%4];"
                 : "=r"(r[0]), "=r"(r[1]), "=r"(r[2]), "=r"(r[3]) : "r"(saddr));
}
__device__ __forceinline__ void mma_bf16(float* c, const unsigned* a, const unsigned* b) {
    asm volatile(
        "mma.sync.aligned.m16n8k16.row.col.f32.bf16.bf16.f32 "
        "{%0,%1,%2,%3}, {%4,%5,%6,%7}, {%8,%9}, {%0,%1,%2,%3};"
        : "+f"(c[0]), "+f"(c[1]), "+f"(c[2]), "+f"(c[3])
        : "r"(a[0]), "r"(a[1]), "r"(a[2]), "r"(a[3]), "r"(b[0]), "r"(b[1]));
}

// ---------------- cs = mean over last axis of cell_mem ----------------
__global__ void k_cs(const float* __restrict__ cell) {
    const int b = blockIdx.x;
    const int t = threadIdx.x;
    const int h = t >> 6, n = t & 63;
    const float4* p = (const float4*)(cell + (((size_t)b * 8 + h) * 64 + n) * 64);
    float s = 0.f;
#pragma unroll
    for (int i = 0; i < 16; ++i) { float4 v = p[i]; s += (v.x + v.y) + (v.z + v.w); }
    g_cs[b * 512 + n * 8 + h] = s * (1.0f / 64.0f);
}

// ---------------- relative-position bias gather ----------------
__global__ void k_bias(const float* __restrict__ rel_table, const int* __restrict__ rel_index) {
    const int i = blockIdx.x * 256 + threadIdx.x;
    const int h = i >> 12, nm = i & 4095;
    g_bias[i] = rel_table[rel_index[nm] * 8 + h];
}

// ---------------- bf16 3-way splits (exact residual decomposition) ----------------
__device__ __forceinline__ void split3(float a, __nv_bfloat16& h0, __nv_bfloat16& h1,
                                       __nv_bfloat16& h2) {
    h0 = __float2bfloat16(a);
    float r1 = a - __bfloat162float(h0);
    h1 = __float2bfloat16(r1);
    float r2 = r1 - __bfloat162float(h1);
    h2 = __float2bfloat16(r2);
}
__global__ void k_split_a(const float* __restrict__ x) {
    const size_t i = ((size_t)blockIdx.x * 256 + threadIdx.x) * 4;
    float4 v = *(const float4*)(x + i);
    __nv_bfloat16 p0[4], p1[4], p2[4];
    split3(v.x, p0[0], p1[0], p2[0]);
    split3(v.y, p0[1], p1[1], p2[1]);
    split3(v.z, p0[2], p1[2], p2[2]);
    split3(v.w, p0[3], p1[3], p2[3]);
    *(uint2*)(g_a0 + i) = *(uint2*)p0;
    *(uint2*)(g_a1 + i) = *(uint2*)p1;
    *(uint2*)(g_a2 + i) = *(uint2*)p2;
}
__global__ void k_split_w(const float* __restrict__ Wq, const float* __restrict__ Wk,
                          const float* __restrict__ Wv, const float* __restrict__ Wo) {
    const size_t i = ((size_t)blockIdx.x * 256 + threadIdx.x) * 4;  // < 262144
    const int row = (int)(i >> 8);
    const float* src = (row < 256) ? Wq : (row < 512) ? Wk : (row < 768) ? Wv : Wo;
    float4 v = *(const float4*)(src + ((size_t)(row & 255) * 256 + (i & 255)));
    __nv_bfloat16 p0[4], p1[4], p2[4];
    split3(v.x, p0[0], p1[0], p2[0]);
    split3(v.y, p0[1], p1[1], p2[1]);
    split3(v.z, p0[2], p1[2], p2[2]);
    split3(v.w, p0[3], p1[3], p2[3]);
    *(uint2*)(g_w0 + i) = *(uint2*)p0;
    *(uint2*)(g_w1 + i) = *(uint2*)p1;
    *(uint2*)(g_w2 + i) = *(uint2*)p2;
}

// ---------------- HMMA GEMM: Y[m, colOff+c] = sum_k A[m,k]*W[c,k], K=256 --------
// 3-way bf16 split with fp32 mma accumulate; pairs (ia,ib) with ia+ib<=3
// (8 pairs: dropped remainder ~2^-32, two orders below fp32 rounding noise).
// Block tile 128x128, 8 warps x (32x64), K staged 64 at a time in swizzled smem.
// Fused BN column stats (sum/sumsq) -> g_pf[rowblock=blockIdx.y].
// mode 0 (QKV): A = g_a0/1/2, B rows/colOff = blockIdx.x*128 (768 cols), Y=g_y.
// mode 1 (O):   A = g_sp (exact 0/1, 3 pairs), B rows 768+bx*128, Y=g_yo (256 cols).
__global__ __launch_bounds__(256) void hgemm(int mode)
{
    extern __shared__ unsigned char smem_raw[];
    const unsigned rawaddr = smem_u32(smem_raw);
    const unsigned pad = (1024u - (rawaddr & 1023u)) & 1023u;
    unsigned char* smem = smem_raw + pad;
    const unsigned sbase = rawaddr + pad;

    const int tid  = threadIdx.x;
    const int lane = tid & 31, wid = tid >> 5;
    const int wm = wid & 3, wn = wid >> 2;   // warp grid 4(m) x 2(n)
    const int m0 = blockIdx.y << 7;
    const int nApl   = mode ? 1 : 3;
    const int brow0  = mode ? (768 + (blockIdx.x << 7)) : (blockIdx.x << 7);
    const int colOff = blockIdx.x << 7;
    float* Y  = mode ? g_yo : g_y;
    const int ldY = mode ? 256 : 768;

    const __nv_bfloat16* APl[3];
    if (mode) { APl[0] = g_sp; APl[1] = g_sp; APl[2] = g_sp; }
    else      { APl[0] = g_a0; APl[1] = g_a1; APl[2] = g_a2; }
    const __nv_bfloat16* BPl[3] = { g_w0, g_w1, g_w2 };

    const unsigned offA[3] = { 0u, 16384u, 32768u };
    const unsigned offB[3] = { 49152u, 65536u, 81920u };

    // ldmatrix lane geometry (canonical m16n8k16 fragment orders)
    const int a_m  = lane & 15;            // row within 16
    const int a_kh = lane >> 4;            // k-half select 0/1
    const int b_n  = (lane & 7) | ((lane & 16) >> 1);  // n row within 16
    const int b_kh = (lane >> 3) & 1;
    int arow[2], brow[4];
#pragma unroll
    for (int mt = 0; mt < 2; ++mt) arow[mt] = wm * 32 + mt * 16 + a_m;
#pragma unroll
    for (int np = 0; np < 4; ++np) brow[np] = wn * 64 + np * 16 + b_n;

    float acc[2][8][4];
#pragma unroll
    for (int mt = 0; mt < 2; ++mt)
#pragma unroll
        for (int nt = 0; nt < 8; ++nt)
#pragma unroll
            for (int j = 0; j < 4; ++j) acc[mt][nt][j] = 0.f;

    for (int kc = 0; kc < 4; ++kc) {
        const int k0 = kc * 64;
        // stage A planes: 128 rows x 64 bf16, 16B-chunk XOR swizzle
        for (int p = 0; p < nApl; ++p) {
            const __nv_bfloat16* src = APl[p] + (size_t)m0 * 256 + k0;
#pragma unroll
            for (int it = 0; it < 4; ++it) {
                const int idx = tid + it * 256;        // 0..1023
                const int row = idx >> 3, ch = idx & 7;
                *(uint4*)(smem + offA[p] + row * 128 + ((ch ^ (row & 7)) << 4)) =
                    *(const uint4*)(src + (size_t)row * 256 + ch * 8);
            }
        }
        // stage B planes: 128 rows x 64 bf16
#pragma unroll
        for (int p = 0; p < 3; ++p) {
            const __nv_bfloat16* src = BPl[p] + (size_t)brow0 * 256 + k0;
#pragma unroll
            for (int it = 0; it < 4; ++it) {
                const int idx = tid + it * 256;
                const int row = idx >> 3, ch = idx & 7;
                *(uint4*)(smem + offB[p] + row * 128 + ((ch ^ (row & 7)) << 4)) =
                    *(const uint4*)(src + (size_t)row * 256 + ch * 8);
            }
        }
        __syncthreads();

#pragma unroll
        for (int ks = 0; ks < 4; ++ks) {
            unsigned af[3][2][4];
#pragma unroll
            for (int ia = 0; ia < 3; ++ia) {
                if (ia >= nApl) break;
#pragma unroll
                for (int mt = 0; mt < 2; ++mt) {
                    const unsigned chunk = (unsigned)(ks * 2 + a_kh);
                    ldsm_x4(af[ia][mt], sbase + offA[ia] + arow[mt] * 128 +
                                        ((chunk ^ (arow[mt] & 7)) << 4));
                }
            }
#pragma unroll
            for (int ib = 0; ib < 3; ++ib) {
                unsigned bf[4][4];   // np -> {b0,b1 of nt=2np, b0,b1 of nt=2np+1}
#pragma unroll
                for (int np = 0; np < 4; ++np) {
                    const unsigned chunk = (unsigned)(ks * 2 + b_kh);
                    ldsm_x4(bf[np], sbase + offB[ib] + brow[np] * 128 +
                                    ((chunk ^ (brow[np] & 7)) << 4));
                }
                // pairs with ia+ib <= 3 (dropped remainder ~2^-32)
                const int iamax = mode ? 1 : ((ib == 2) ? 2 : 3);
                for (int ia = 0; ia < iamax; ++ia)
#pragma unroll
                    for (int mt = 0; mt < 2; ++mt)
#pragma unroll
                        for (int nt = 0; nt < 8; ++nt)
                            mma_bf16(acc[mt][nt], af[ia][mt], &bf[nt >> 1][(nt & 1) * 2]);
            }
        }
        __syncthreads();
    }

    // ---- store tile (c0,c1 -> row l/4; c2,c3 -> row l/4+8) ----
    const int lrow = lane >> 2, lcp = (lane & 3) * 2;
#pragma unroll
    for (int mt = 0; mt < 2; ++mt) {
        const int row = m0 + wm * 32 + mt * 16 + lrow;
        float* yr  = Y + (size_t)row * ldY + colOff + wn * 64;
        float* yr2 = yr + 8 * (size_t)ldY;
#pragma unroll
        for (int nt = 0; nt < 8; ++nt) {
            *(float2*)(yr  + nt * 8 + lcp) = make_float2(acc[mt][nt][0], acc[mt][nt][1]);
            *(float2*)(yr2 + nt * 8 + lcp) = make_float2(acc[mt][nt][2], acc[mt][nt][3]);
        }
    }

    // ---- fused BN column stats: per-lane partial, shfl tree, smem reduce ----
    float cs[8][2], cq[8][2];
#pragma unroll
    for (int nt = 0; nt < 8; ++nt) {
        cs[nt][0] = (acc[0][nt][0] + acc[0][nt][2]) + (acc[1][nt][0] + acc[1][nt][2]);
        cs[nt][1] = (acc[0][nt][1] + acc[0][nt][3]) + (acc[1][nt][1] + acc[1][nt][3]);
        float q0 = acc[0][nt][0] * acc[0][nt][0];
        q0 = fmaf(acc[0][nt][2], acc[0][nt][2], q0);
        q0 = fmaf(acc[1][nt][0], acc[1][nt][0], q0);
        q0 = fmaf(acc[1][nt][2], acc[1][nt][2], q0);
        cq[nt][0] = q0;
        float q1 = acc[0][nt][1] * acc[0][nt][1];
        q1 = fmaf(acc[0][nt][3], acc[0][nt][3], q1);
        q1 = fmaf(acc[1][nt][1], acc[1][nt][1], q1);
        q1 = fmaf(acc[1][nt][3], acc[1][nt][3], q1);
        cq[nt][1] = q1;
    }
#pragma unroll
    for (int off = 4; off < 32; off <<= 1)
#pragma unroll
        for (int nt = 0; nt < 8; ++nt) {
            cs[nt][0] += __shfl_xor_sync(0xffffffffu, cs[nt][0], off);
            cs[nt][1] += __shfl_xor_sync(0xffffffffu, cs[nt][1], off);
            cq[nt][0] += __shfl_xor_sync(0xffffffffu, cq[nt][0], off);
            cq[nt][1] += __shfl_xor_sync(0xffffffffu, cq[nt][1], off);
        }
    __syncthreads();                         // smem tiles no longer needed
    float* redS = (float*)smem;              // [4][128]
    float* redQ = redS + 512;                // [4][128]
    if (lane < 4) {
#pragma unroll
        for (int nt = 0; nt < 8; ++nt) {
            const int col = wn * 64 + nt * 8 + lane * 2;
            redS[wm * 128 + col]     = cs[nt][0];
            redS[wm * 128 + col + 1] = cs[nt][1];
            redQ[wm * 128 + col]     = cq[nt][0];
            redQ[wm * 128 + col + 1] = cq[nt][1];
        }
    }
    __syncthreads();
    if (tid < 128) {
        float s = (redS[tid] + redS[128 + tid]) + (redS[256 + tid] + redS[384 + tid]);
        float q = (redQ[tid] + redQ[128 + tid]) + (redQ[256 + tid] + redQ[384 + tid]);
        g_pf[(size_t)blockIdx.y * 1536 + colOff + tid]       = s;
        g_pf[(size_t)blockIdx.y * 1536 + 768 + colOff + tid] = q;
    }
}

// ---------------- BN stats finalize: Kahan-fp32 over 512 partials ----------------
// One block per 256-channel group: blockIdx.x selects (gamma,beta,colOff) set.
__global__ void k_stats_final3(const float* __restrict__ g0, const float* __restrict__ b0,
                               const float* __restrict__ g1, const float* __restrict__ b1,
                               const float* __restrict__ g2, const float* __restrict__ b2) {
    const int grp = blockIdx.x;
    const float* gamma = (grp == 0) ? g0 : (grp == 1) ? g1 : g2;
    const float* beta  = (grp == 0) ? b0 : (grp == 1) ? b1 : b2;
    const int colOff = grp << 8;
    const int c = colOff + threadIdx.x;
    float s = 0.f, cs = 0.f, q = 0.f, cq = 0.f;
    for (int b = 0; b < 512; ++b) {
        float v  = g_pf[(size_t)b * 1536 + c];
        float y  = v - cs; float t  = s + y;  cs = (t - s) - y;  s = t;
        float w  = g_pf[(size_t)b * 1536 + 768 + c];
        float y2 = w - cq; float t2 = q + y2; cq = (t2 - q) - y2; q = t2;
    }
    const double mean = (double)s * (1.0 / 65536.0);
    const double var  = (double)q * (1.0 / 65536.0) - mean * mean;
    const double rs   = 1.0 / sqrt(var + 1e-5);
    const double g    = (double)gamma[threadIdx.x];
    g_scale[c] = (float)(g * rs);
    g_shift[c] = (float)((double)beta[threadIdx.x] - g * rs * mean);
}
__global__ void k_stats_final_o(const float* __restrict__ gamma, const float* __restrict__ beta) {
    const int c = threadIdx.x;
    float s = 0.f, cs = 0.f, q = 0.f, cq = 0.f;
    for (int b = 0; b < 512; ++b) {
        float v  = g_pf[(size_t)b * 1536 + c];
        float y  = v - cs; float t  = s + y;  cs = (t - s) - y;  s = t;
        float w  = g_pf[(size_t)b * 1536 + 768 + c];
        float y2 = w - cq; float t2 = q + y2; cq = (t2 - q) - y2; q = t2;
    }
    const double mean = (double)s * (1.0 / 65536.0);
    const double var  = (double)q * (1.0 / 65536.0) - mean * mean;
    const double rs   = 1.0 / sqrt(var + 1e-5);
    const double g    = (double)gamma[c];
    g_scale_o[c] = (float)(g * rs);
    g_shift_o[c] = (float)((double)beta[c] - g * rs * mean);
}

// ---------------- Q/K/V epilogue: BN + feedback + LIF + bit-pack ----------------
__global__ __launch_bounds__(256) void k_qkv_epi(
    const float* __restrict__ qmem, const float* __restrict__ kmem,
    const float* __restrict__ vmem,
    const float* __restrict__ Wfb, const float* __restrict__ bfb,
    const float* __restrict__ betas, float* __restrict__ ob)
{
    const int c    = threadIdx.x;
    const int lane = c & 31;
    const int h    = c >> 5;
    float wf[8];
#pragma unroll
    for (int j = 0; j < 8; ++j) wf[j] = Wfb[c * 8 + j];
    const float bfbc = bfb[c];
    const float b0 = betas[0], b1 = betas[1], b2 = betas[2];
    const float sq = g_scale[c],       hq = g_shift[c];
    const float sk = g_scale[256 + c], hk = g_shift[256 + c];
    const float sv = g_scale[512 + c], hv = g_shift[512 + c];

    const int r0 = blockIdx.x * 16;
    for (int rr = 0; rr < 16; ++rr) {
        const int r = r0 + rr;
        const int b = r >> 6, n = r & 63;
        const float* csp = g_cs + b * 512 + n * 8;
        float fb = bfbc;
#pragma unroll
        for (int j = 0; j < 8; ++j) fb = fmaf(csp[j], wf[j], fb);

        const size_t yo = (size_t)r * 768 + c;
        const size_t mo = (size_t)r * 256 + c;
        const int bitidx = (b * 8 + h) * 64 + n;
        {
            float pre = fmaf(g_y[yo], sq, hq) + fb;
            float mem = fmaf(b0, qmem[mo], pre);
            bool  s   = mem > 1.0f;
            ob[O_QM + mo] = s ? (mem - 1.0f) : mem;
            unsigned bits = __ballot_sync(0xffffffffu, s);
            if (lane == 0) g_qbits[bitidx] = bits;
        }
        {
            float pre = fmaf(g_y[yo + 256], sk, hk) + fb;
            float mem = fmaf(b1, kmem[mo], pre);
            bool  s   = mem > 1.0f;
            ob[O_KM + mo] = s ? (mem - 1.0f) : mem;
            unsigned bits = __ballot_sync(0xffffffffu, s);
            if (lane == 0) g_kbits[bitidx] = bits;
        }
        {
            float pre = fmaf(g_y[yo + 512], sv, hv) + fb;
            float mem = fmaf(b2, vmem[mo], pre);
            bool  s   = mem > 1.0f;
            ob[O_VM + mo] = s ? (mem - 1.0f) : mem;
            unsigned bits = __ballot_sync(0xffffffffu, s);
            if (lane == 0) g_vbits[bitidx] = bits;
        }
    }
}

// ---------------- attention: gate -> cell LIF (zero reset) -> attn@v -> attn LIF --
__global__ __launch_bounds__(64) void k_attn(
    const float* __restrict__ cellmem, const float* __restrict__ attnmem,
    const int* __restrict__ mask, const float* __restrict__ betas,
    float* __restrict__ ob)
{
    const int bh = blockIdx.x;
    const int b = bh >> 3, h = bh & 7, w = b & 63;
    const int n = threadIdx.x;

    __shared__ unsigned kb[64], vb[64];
    __shared__ unsigned long long vT[32];

    kb[n] = g_kbits[bh * 64 + n];
    vb[n] = g_vbits[bh * 64 + n];
    __syncthreads();
    if (n < 32) {
        unsigned long long t = 0ull;
#pragma unroll
        for (int m = 0; m < 64; ++m)
            t |= (unsigned long long)((vb[m] >> n) & 1u) << m;
        vT[n] = t;
    }
    const unsigned q = g_qbits[bh * 64 + n];
    const float b3 = betas[3], b4 = betas[4];

    const float4* bias4 = (const float4*)(g_bias + h * 4096 + n * 64);
    const int4*   mp4   = (const int4*)(mask + w * 4096 + n * 64);
    const float4* cp4   = (const float4*)(cellmem + ((size_t)bh * 64 + n) * 64);
    float4*       cn4   = (float4*)(ob + O_CELL + ((size_t)bh * 64 + n) * 64);

    __syncthreads();

    unsigned long long amask = 0ull;
#pragma unroll 4
    for (int mq = 0; mq < 16; ++mq) {
        float4 bv = bias4[mq];
        int4   mv = mp4[mq];
        float4 cv = cp4[mq];
        float4 co;
        {
            int m = mq * 4 + 0;
            float gate = fmaf((float)__popc(q & kb[m]), 0.125f, bv.x);
            if (mv.x != 0) gate = 0.0f;
            float mem = fmaf(b3, cv.x, gate);
            bool  s   = mem > 1.0f;
            co.x = s ? 0.0f : mem;
            amask |= (unsigned long long)(s ? 1 : 0) << m;
        }
        {
            int m = mq * 4 + 1;
            float gate = fmaf((float)__popc(q & kb[m]), 0.125f, bv.y);
            if (mv.y != 0) gate = 0.0f;
            float mem = fmaf(b3, cv.y, gate);
            bool  s   = mem > 1.0f;
            co.y = s ? 0.0f : mem;
            amask |= (unsigned long long)(s ? 1 : 0) << m;
        }
        {
            int m = mq * 4 + 2;
            float gate = fmaf((float)__popc(q & kb[m]), 0.125f, bv.z);
            if (mv.z != 0) gate = 0.0f;
            float mem = fmaf(b3, cv.z, gate);
            bool  s   = mem > 1.0f;
            co.z = s ? 0.0f : mem;
            amask |= (unsigned long long)(s ? 1 : 0) << m;
        }
        {
            int m = mq * 4 + 3;
            float gate = fmaf((float)__popc(q & kb[m]), 0.125f, bv.w);
            if (mv.w != 0) gate = 0.0f;
            float mem = fmaf(b3, cv.w, gate);
            bool  s   = mem > 1.0f;
            co.w = s ? 0.0f : mem;
            amask |= (unsigned long long)(s ? 1 : 0) << m;
        }
        cn4[mq] = co;
    }

    const size_t arow = ((size_t)b * 64 + n) * 256 + h * 32;
    const float*   ap  = attnmem + arow;
    float*         amp = ob + O_AM + arow;
    __nv_bfloat16* o2  = g_sp + arow;
#pragma unroll 8
    for (int d2 = 0; d2 < 32; ++d2) {
        float o   = (float)__popcll(amask & vT[d2]) * 0.25f;
        float mem = fmaf(b4, ap[d2], o);
        float s   = mem > 0.5f ? 1.0f : 0.0f;
        amp[d2] = mem - 0.5f * s;
        o2[d2]  = __float2bfloat16(s);   // exact 0/1
    }
}

// ---------------- final epilogue: BN(o) + LIF -> out spikes + om ----------------
__global__ void k_out_epi(const float* __restrict__ outmem,
                          const float* __restrict__ betas,
                          float* __restrict__ ob)
{
    const size_t i = (size_t)blockIdx.x * 256 + threadIdx.x;
    const int c = (int)(i & 255);
    float y   = fmaf(g_yo[i], g_scale_o[c], g_shift_o[c]);
    float mem = fmaf(betas[5], outmem[i], y);
    float s   = mem > 1.0f ? 1.0f : 0.0f;
    ob[i]        = s;
    ob[O_OM + i] = mem - s;
}

// ---------------- launch ----------------
extern "C" void kernel_launch(void* const* d_in, const int* in_sizes, int n_in,
                              void* d_out, int out_size)
{
    const float* x       = (const float*)d_in[0];
    const float* qmem    = (const float*)d_in[1];
    const float* kmem    = (const float*)d_in[2];
    const float* vmem    = (const float*)d_in[3];
    const float* cellmem = (const float*)d_in[4];
    const float* attnmem = (const float*)d_in[5];
    const float* outmem  = (const float*)d_in[6];
    const float* Wq  = (const float*)d_in[7];
    const float* gq  = (const float*)d_in[9];
    const float* btq = (const float*)d_in[10];
    const float* Wk  = (const float*)d_in[11];
    const float* gk  = (const float*)d_in[13];
    const float* btk = (const float*)d_in[14];
    const float* Wv  = (const float*)d_in[15];
    const float* gv  = (const float*)d_in[17];
    const float* btv = (const float*)d_in[18];
    const float* Wfb = (const float*)d_in[19];
    const float* bfb = (const float*)d_in[20];
    const float* Wo  = (const float*)d_in[21];
    const float* go  = (const float*)d_in[23];
    const float* bto = (const float*)d_in[24];
    const float* rel_table = (const float*)d_in[25];
    const float* betas     = (const float*)d_in[26];
    const int*   mask      = (const int*)d_in[27];
    const int*   rel_index = (const int*)d_in[28];
    float* ob = (float*)d_out;

    // 98304 staging + 1024 alignment slack
    cudaFuncSetAttribute(hgemm, cudaFuncAttributeMaxDynamicSharedMemorySize, 99328);

    k_cs     <<<1024, 512>>>(cellmem);
    k_bias   <<<128, 256>>>(rel_table, rel_index);
    k_split_a<<<16384, 256>>>(x);
    k_split_w<<<256, 256>>>(Wq, Wk, Wv, Wo);

    // QKV GEMM: N-block fast in grid.x for L2 reuse of A across the 6 col-blocks
    dim3 gq3(6, 512);
    hgemm<<<gq3, 256, 99328>>>(0);

    k_stats_final3<<<3, 256>>>(gq, btq, gk, btk, gv, btv);

    k_qkv_epi<<<4096, 256>>>(qmem, kmem, vmem, Wfb, bfb, betas, ob);
    k_attn   <<<8192, 64>>>(cellmem, attnmem, mask, betas, ob);

    dim3 go1(2, 512);
    hgemm<<<go1, 256, 99328>>>(1);
    k_stats_final_o<<<1, 256>>>(go, bto);

    k_out_epi<<<65536, 256>>>(outmem, betas, ob);
}

// round 15
// speedup vs baseline: 1.2243x; 1.2243x over previous
#include <cuda_runtime.h>
#include <cuda_bf16.h>
#include <math.h>

// Problem constants (fixed by setup_inputs):
// B=16, nW=64, BnW=1024, N=64, C=256, H=8, d=32, rows R=65536
static const size_t SEG    = 16777216ull;
static const size_t O_QM   = 1ull * SEG;
static const size_t O_KM   = 2ull * SEG;
static const size_t O_VM   = 3ull * SEG;
static const size_t O_CELL = 4ull * SEG;
static const size_t O_AM   = 6ull * SEG;
static const size_t O_OM   = 7ull * SEG;

// ---------------- static device scratch (no allocations) ----------------
__device__ float          g_y[50331648];     // pre-BN q|k|v activations (65536 x 768)
__device__ float          g_yo[16777216];    // pre-BN o activations (65536 x 256)
__device__ __nv_bfloat16  g_a0[16777216];    // bf16 split planes of x (65536 x 256)
__device__ __nv_bfloat16  g_a1[16777216];
__device__ __nv_bfloat16  g_a2[16777216];
__device__ __nv_bfloat16  g_sp[16777216];    // attn-LIF spikes as bf16 (exact 0/1)
__device__ __nv_bfloat16  g_w0[262144];      // bf16 split planes of [Wq;Wk;Wv;Wo] (1024 x 256)
__device__ __nv_bfloat16  g_w1[262144];
__device__ __nv_bfloat16  g_w2[262144];
__device__ float          g_cs[524288];      // (BnW, N, H) coincidence state
__device__ float          g_bias[32768];     // (H, N, N) relative position bias
__device__ unsigned       g_qbits[524288];   // (BnW, H, N): packed spikes over d=32
__device__ unsigned       g_kbits[524288];
__device__ unsigned       g_vbits[524288];
__device__ float          g_pf[786432];      // stats partials: 512 rowblocks x (768 sum | 768 sumsq)
__device__ float          g_scale[768], g_shift[768];
__device__ float          g_scale_o[256], g_shift_o[256];

// ---------------- warp mma helpers (legacy path, plain sm_103) ----------------
__device__ __forceinline__ unsigned smem_u32(const void* p) {
    return (unsigned)__cvta_generic_to_shared(p);
}
__device__ __forceinline__ void ldsm_x4(unsigned r[4], unsigned saddr) {
    asm volatile("ldmatrix.sync.aligned.m8n8.x4.shared.b16 {%0,%1,%2,%3}, [%4];"
                 : "=r"(r[0]), "=r"(r[1]), "=r"(r[2]), "=r"(r[3]) : "r"(saddr));
}
__device__ __forceinline__ void mma_bf16(float* c, const unsigned* a, const unsigned* b) {
    asm volatile(
        "mma.sync.aligned.m16n8k16.row.col.f32.bf16.bf16.f32 "
        "{%0,%1,%2,%3}, {%4,%5,%6,%7}, {%8,%9}, {%0,%1,%2,%3};"
        : "+f"(c[0]), "+f"(c[1]), "+f"(c[2]), "+f"(c[3])
        : "r"(a[0]), "r"(a[1]), "r"(a[2]), "r"(a[3]), "r"(b[0]), "r"(b[1]));
}
__device__ __forceinline__ void cp16(unsigned dst, const void* src) {
    asm volatile("cp.async.cg.shared.global [%0], [%1], 16;" :: "r"(dst), "l"(src));
}
#define CP_COMMIT() asm volatile("cp.async.commit_group;" ::: "memory")
#define CP_WAIT0()  asm volatile("cp.async.wait_group 0;" ::: "memory")
#define CP_WAIT1()  asm volatile("cp.async.wait_group 1;" ::: "memory")

// ---------------- cs = mean over last axis of cell_mem ----------------
__global__ void k_cs(const float* __restrict__ cell) {
    const int b = blockIdx.x;
    const int t = threadIdx.x;
    const int h = t >> 6, n = t & 63;
    const float4* p = (const float4*)(cell + (((size_t)b * 8 + h) * 64 + n) * 64);
    float s = 0.f;
#pragma unroll
    for (int i = 0; i < 16; ++i) { float4 v = p[i]; s += (v.x + v.y) + (v.z + v.w); }
    g_cs[b * 512 + n * 8 + h] = s * (1.0f / 64.0f);
}

// ---------------- relative-position bias gather ----------------
__global__ void k_bias(const float* __restrict__ rel_table, const int* __restrict__ rel_index) {
    const int i = blockIdx.x * 256 + threadIdx.x;
    const int h = i >> 12, nm = i & 4095;
    g_bias[i] = rel_table[rel_index[nm] * 8 + h];
}

// ---------------- bf16 3-way splits (exact residual decomposition) ----------------
__device__ __forceinline__ void split3(float a, __nv_bfloat16& h0, __nv_bfloat16& h1,
                                       __nv_bfloat16& h2) {
    h0 = __float2bfloat16(a);
    float r1 = a - __bfloat162float(h0);
    h1 = __float2bfloat16(r1);
    float r2 = r1 - __bfloat162float(h1);
    h2 = __float2bfloat16(r2);
}
__global__ void k_split_a(const float* __restrict__ x) {
    const size_t i = ((size_t)blockIdx.x * 256 + threadIdx.x) * 4;
    float4 v = *(const float4*)(x + i);
    __nv_bfloat16 p0[4], p1[4], p2[4];
    split3(v.x, p0[0], p1[0], p2[0]);
    split3(v.y, p0[1], p1[1], p2[1]);
    split3(v.z, p0[2], p1[2], p2[2]);
    split3(v.w, p0[3], p1[3], p2[3]);
    *(uint2*)(g_a0 + i) = *(uint2*)p0;
    *(uint2*)(g_a1 + i) = *(uint2*)p1;
    *(uint2*)(g_a2 + i) = *(uint2*)p2;
}
__global__ void k_split_w(const float* __restrict__ Wq, const float* __restrict__ Wk,
                          const float* __restrict__ Wv, const float* __restrict__ Wo) {
    const size_t i = ((size_t)blockIdx.x * 256 + threadIdx.x) * 4;  // < 262144
    const int row = (int)(i >> 8);
    const float* src = (row < 256) ? Wq : (row < 512) ? Wk : (row < 768) ? Wv : Wo;
    float4 v = *(const float4*)(src + ((size_t)(row & 255) * 256 + (i & 255)));
    __nv_bfloat16 p0[4], p1[4], p2[4];
    split3(v.x, p0[0], p1[0], p2[0]);
    split3(v.y, p0[1], p1[1], p2[1]);
    split3(v.z, p0[2], p1[2], p2[2]);
    split3(v.w, p0[3], p1[3], p2[3]);
    *(uint2*)(g_w0 + i) = *(uint2*)p0;
    *(uint2*)(g_w1 + i) = *(uint2*)p1;
    *(uint2*)(g_w2 + i) = *(uint2*)p2;
}

// ---------------- HMMA GEMM: Y[m, colOff+c] = sum_k A[m,k]*W[c,k], K=256 --------
// 3-way bf16 split, fp32 mma accumulate; pairs (ia,ib) with ia+ib<=2 (R13 scheme;
// R14 showed more pairs leave rel_err bitwise unchanged).
// Block tile 128x128, 8 warps x (32x64); K staged 64/chunk, cp.async DOUBLE-
// BUFFERED so chunk kc+1 streams in while chunk kc is computed (1 CTA/SM).
// Fused BN column stats (sum/sumsq) -> g_pf[rowblock=blockIdx.y].
// mode 0 (QKV): A = g_a0/1/2, B rows/colOff = blockIdx.x*128 (768 cols), Y=g_y.
// mode 1 (O):   A = g_sp (exact 0/1, 3 pairs), B rows 768+bx*128, Y=g_yo (256 cols).
__global__ __launch_bounds__(256) void hgemm(int mode)
{
    extern __shared__ unsigned char smem_raw[];
    const unsigned rawaddr = smem_u32(smem_raw);
    const unsigned pad = (1024u - (rawaddr & 1023u)) & 1023u;
    unsigned char* smem = smem_raw + pad;
    const unsigned sbase = rawaddr + pad;

    const int tid  = threadIdx.x;
    const int lane = tid & 31, wid = tid >> 5;
    const int wm = wid & 3, wn = wid >> 2;   // warp grid 4(m) x 2(n)
    const int m0 = blockIdx.y << 7;
    const int nApl   = mode ? 1 : 3;
    const int brow0  = mode ? (768 + (blockIdx.x << 7)) : (blockIdx.x << 7);
    const int colOff = blockIdx.x << 7;
    float* Y  = mode ? g_yo : g_y;
    const int ldY = mode ? 256 : 768;

    const __nv_bfloat16* APl[3];
    if (mode) { APl[0] = g_sp; APl[1] = g_sp; APl[2] = g_sp; }
    else      { APl[0] = g_a0; APl[1] = g_a1; APl[2] = g_a2; }
    const __nv_bfloat16* BPl[3] = { g_w0, g_w1, g_w2 };

    const unsigned STG = 98304u;                    // bytes per pipeline stage
    const unsigned offA[3] = { 0u, 16384u, 32768u };
    const unsigned offB[3] = { 49152u, 65536u, 81920u };

    // cp.async staging of one K64 chunk into stage st
    auto stage_chunk = [&](int kc, int st) {
        const int k0 = kc * 64;
        const unsigned base = sbase + (unsigned)st * STG;
        for (int p = 0; p < nApl; ++p) {
            const __nv_bfloat16* src = APl[p] + (size_t)m0 * 256 + k0;
#pragma unroll
            for (int it = 0; it < 4; ++it) {
                const int idx = tid + it * 256;        // 0..1023
                const int row = idx >> 3, ch = idx & 7;
                cp16(base + offA[p] + row * 128 + ((ch ^ (row & 7)) << 4),
                     src + (size_t)row * 256 + ch * 8);
            }
        }
#pragma unroll
        for (int p = 0; p < 3; ++p) {
            const __nv_bfloat16* src = BPl[p] + (size_t)brow0 * 256 + k0;
#pragma unroll
            for (int it = 0; it < 4; ++it) {
                const int idx = tid + it * 256;
                const int row = idx >> 3, ch = idx & 7;
                cp16(base + offB[p] + row * 128 + ((ch ^ (row & 7)) << 4),
                     src + (size_t)row * 256 + ch * 8);
            }
        }
    };

    // ldmatrix lane geometry (canonical m16n8k16 fragment orders)
    const int a_m  = lane & 15;            // row within 16
    const int a_kh = lane >> 4;            // k-half select 0/1
    const int b_n  = (lane & 7) | ((lane & 16) >> 1);  // n row within 16
    const int b_kh = (lane >> 3) & 1;
    int arow[2], brow[4];
#pragma unroll
    for (int mt = 0; mt < 2; ++mt) arow[mt] = wm * 32 + mt * 16 + a_m;
#pragma unroll
    for (int np = 0; np < 4; ++np) brow[np] = wn * 64 + np * 16 + b_n;

    float acc[2][8][4];
#pragma unroll
    for (int mt = 0; mt < 2; ++mt)
#pragma unroll
        for (int nt = 0; nt < 8; ++nt)
#pragma unroll
            for (int j = 0; j < 4; ++j) acc[mt][nt][j] = 0.f;

    stage_chunk(0, 0);
    CP_COMMIT();

    int st = 0;
    for (int kc = 0; kc < 4; ++kc) {
        if (kc < 3) { stage_chunk(kc + 1, st ^ 1); CP_COMMIT(); CP_WAIT1(); }
        else        { CP_WAIT0(); }
        __syncthreads();

        const unsigned base = sbase + (unsigned)st * STG;
#pragma unroll
        for (int ks = 0; ks < 4; ++ks) {
            unsigned af[3][2][4];
#pragma unroll
            for (int ia = 0; ia < 3; ++ia) {
                if (ia >= nApl) break;
#pragma unroll
                for (int mt = 0; mt < 2; ++mt) {
                    const unsigned chunk = (unsigned)(ks * 2 + a_kh);
                    ldsm_x4(af[ia][mt], base + offA[ia] + arow[mt] * 128 +
                                        ((chunk ^ (arow[mt] & 7)) << 4));
                }
            }
#pragma unroll
            for (int ib = 0; ib < 3; ++ib) {
                unsigned bf[4][4];   // np -> {b0,b1 of nt=2np, b0,b1 of nt=2np+1}
#pragma unroll
                for (int np = 0; np < 4; ++np) {
                    const unsigned chunk = (unsigned)(ks * 2 + b_kh);
                    ldsm_x4(bf[np], base + offB[ib] + brow[np] * 128 +
                                    ((chunk ^ (brow[np] & 7)) << 4));
                }
                // pairs with ia+ib <= 2 (R13 scheme)
                const int iamax = (nApl < 3 - ib) ? nApl : (3 - ib);
                for (int ia = 0; ia < iamax; ++ia)
#pragma unroll
                    for (int mt = 0; mt < 2; ++mt)
#pragma unroll
                        for (int nt = 0; nt < 8; ++nt)
                            mma_bf16(acc[mt][nt], af[ia][mt], &bf[nt >> 1][(nt & 1) * 2]);
            }
        }
        __syncthreads();           // all warps done with stage st before reuse
        st ^= 1;
    }

    // ---- store tile (c0,c1 -> row l/4; c2,c3 -> row l/4+8) ----
    const int lrow = lane >> 2, lcp = (lane & 3) * 2;
#pragma unroll
    for (int mt = 0; mt < 2; ++mt) {
        const int row = m0 + wm * 32 + mt * 16 + lrow;
        float* yr  = Y + (size_t)row * ldY + colOff + wn * 64;
        float* yr2 = yr + 8 * (size_t)ldY;
#pragma unroll
        for (int nt = 0; nt < 8; ++nt) {
            *(float2*)(yr  + nt * 8 + lcp) = make_float2(acc[mt][nt][0], acc[mt][nt][1]);
            *(float2*)(yr2 + nt * 8 + lcp) = make_float2(acc[mt][nt][2], acc[mt][nt][3]);
        }
    }

    // ---- fused BN column stats: per-lane partial, shfl tree, smem reduce ----
    float cs[8][2], cq[8][2];
#pragma unroll
    for (int nt = 0; nt < 8; ++nt) {
        cs[nt][0] = (acc[0][nt][0] + acc[0][nt][2]) + (acc[1][nt][0] + acc[1][nt][2]);
        cs[nt][1] = (acc[0][nt][1] + acc[0][nt][3]) + (acc[1][nt][1] + acc[1][nt][3]);
        float q0 = acc[0][nt][0] * acc[0][nt][0];
        q0 = fmaf(acc[0][nt][2], acc[0][nt][2], q0);
        q0 = fmaf(acc[1][nt][0], acc[1][nt][0], q0);
        q0 = fmaf(acc[1][nt][2], acc[1][nt][2], q0);
        cq[nt][0] = q0;
        float q1 = acc[0][nt][1] * acc[0][nt][1];
        q1 = fmaf(acc[0][nt][3], acc[0][nt][3], q1);
        q1 = fmaf(acc[1][nt][1], acc[1][nt][1], q1);
        q1 = fmaf(acc[1][nt][3], acc[1][nt][3], q1);
        cq[nt][1] = q1;
    }
#pragma unroll
    for (int off = 4; off < 32; off <<= 1)
#pragma unroll
        for (int nt = 0; nt < 8; ++nt) {
            cs[nt][0] += __shfl_xor_sync(0xffffffffu, cs[nt][0], off);
            cs[nt][1] += __shfl_xor_sync(0xffffffffu, cs[nt][1], off);
            cq[nt][0] += __shfl_xor_sync(0xffffffffu, cq[nt][0], off);
            cq[nt][1] += __shfl_xor_sync(0xffffffffu, cq[nt][1], off);
        }
    __syncthreads();                         // smem tiles no longer needed
    float* redS = (float*)smem;              // [4][128]
    float* redQ = redS + 512;                // [4][128]
    if (lane < 4) {
#pragma unroll
        for (int nt = 0; nt < 8; ++nt) {
            const int col = wn * 64 + nt * 8 + lane * 2;
            redS[wm * 128 + col]     = cs[nt][0];
            redS[wm * 128 + col + 1] = cs[nt][1];
            redQ[wm * 128 + col]     = cq[nt][0];
            redQ[wm * 128 + col + 1] = cq[nt][1];
        }
    }
    __syncthreads();
    if (tid < 128) {
        float s = (redS[tid] + redS[128 + tid]) + (redS[256 + tid] + redS[384 + tid]);
        float q = (redQ[tid] + redQ[128 + tid]) + (redQ[256 + tid] + redQ[384 + tid]);
        g_pf[(size_t)blockIdx.y * 1536 + colOff + tid]       = s;
        g_pf[(size_t)blockIdx.y * 1536 + 768 + colOff + tid] = q;
    }
}

// ---------------- BN stats finalize: Kahan-fp32 over 512 partials ----------------
__global__ void k_stats_final3(const float* __restrict__ g0, const float* __restrict__ b0,
                               const float* __restrict__ g1, const float* __restrict__ b1,
                               const float* __restrict__ g2, const float* __restrict__ b2) {
    const int grp = blockIdx.x;
    const float* gamma = (grp == 0) ? g0 : (grp == 1) ? g1 : g2;
    const float* beta  = (grp == 0) ? b0 : (grp == 1) ? b1 : b2;
    const int colOff = grp << 8;
    const int c = colOff + threadIdx.x;
    float s = 0.f, cs = 0.f, q = 0.f, cq = 0.f;
    for (int b = 0; b < 512; ++b) {
        float v  = g_pf[(size_t)b * 1536 + c];
        float y  = v - cs; float t  = s + y;  cs = (t - s) - y;  s = t;
        float w  = g_pf[(size_t)b * 1536 + 768 + c];
        float y2 = w - cq; float t2 = q + y2; cq = (t2 - q) - y2; q = t2;
    }
    const double mean = (double)s * (1.0 / 65536.0);
    const double var  = (double)q * (1.0 / 65536.0) - mean * mean;
    const double rs   = 1.0 / sqrt(var + 1e-5);
    const double g    = (double)gamma[threadIdx.x];
    g_scale[c] = (float)(g * rs);
    g_shift[c] = (float)((double)beta[threadIdx.x] - g * rs * mean);
}
__global__ void k_stats_final_o(const float* __restrict__ gamma, const float* __restrict__ beta) {
    const int c = threadIdx.x;
    float s = 0.f, cs = 0.f, q = 0.f, cq = 0.f;
    for (int b = 0; b < 512; ++b) {
        float v  = g_pf[(size_t)b * 1536 + c];
        float y  = v - cs; float t  = s + y;  cs = (t - s) - y;  s = t;
        float w  = g_pf[(size_t)b * 1536 + 768 + c];
        float y2 = w - cq; float t2 = q + y2; cq = (t2 - q) - y2; q = t2;
    }
    const double mean = (double)s * (1.0 / 65536.0);
    const double var  = (double)q * (1.0 / 65536.0) - mean * mean;
    const double rs   = 1.0 / sqrt(var + 1e-5);
    const double g    = (double)gamma[c];
    g_scale_o[c] = (float)(g * rs);
    g_shift_o[c] = (float)((double)beta[c] - g * rs * mean);
}

// ---------------- Q/K/V epilogue: BN + feedback + LIF + bit-pack ----------------
__global__ __launch_bounds__(256) void k_qkv_epi(
    const float* __restrict__ qmem, const float* __restrict__ kmem,
    const float* __restrict__ vmem,
    const float* __restrict__ Wfb, const float* __restrict__ bfb,
    const float* __restrict__ betas, float* __restrict__ ob)
{
    const int c    = threadIdx.x;
    const int lane = c & 31;
    const int h    = c >> 5;
    float wf[8];
#pragma unroll
    for (int j = 0; j < 8; ++j) wf[j] = Wfb[c * 8 + j];
    const float bfbc = bfb[c];
    const float b0 = betas[0], b1 = betas[1], b2 = betas[2];
    const float sq = g_scale[c],       hq = g_shift[c];
    const float sk = g_scale[256 + c], hk = g_shift[256 + c];
    const float sv = g_scale[512 + c], hv = g_shift[512 + c];

    const int r0 = blockIdx.x * 16;
    for (int rr = 0; rr < 16; ++rr) {
        const int r = r0 + rr;
        const int b = r >> 6, n = r & 63;
        const float* csp = g_cs + b * 512 + n * 8;
        float fb = bfbc;
#pragma unroll
        for (int j = 0; j < 8; ++j) fb = fmaf(csp[j], wf[j], fb);

        const size_t yo = (size_t)r * 768 + c;
        const size_t mo = (size_t)r * 256 + c;
        const int bitidx = (b * 8 + h) * 64 + n;
        {
            float pre = fmaf(g_y[yo], sq, hq) + fb;
            float mem = fmaf(b0, qmem[mo], pre);
            bool  s   = mem > 1.0f;
            ob[O_QM + mo] = s ? (mem - 1.0f) : mem;
            unsigned bits = __ballot_sync(0xffffffffu, s);
            if (lane == 0) g_qbits[bitidx] = bits;
        }
        {
            float pre = fmaf(g_y[yo + 256], sk, hk) + fb;
            float mem = fmaf(b1, kmem[mo], pre);
            bool  s   = mem > 1.0f;
            ob[O_KM + mo] = s ? (mem - 1.0f) : mem;
            unsigned bits = __ballot_sync(0xffffffffu, s);
            if (lane == 0) g_kbits[bitidx] = bits;
        }
        {
            float pre = fmaf(g_y[yo + 512], sv, hv) + fb;
            float mem = fmaf(b2, vmem[mo], pre);
            bool  s   = mem > 1.0f;
            ob[O_VM + mo] = s ? (mem - 1.0f) : mem;
            unsigned bits = __ballot_sync(0xffffffffu, s);
            if (lane == 0) g_vbits[bitidx] = bits;
        }
    }
}

// ---------------- attention: gate -> cell LIF (zero reset) -> attn@v -> attn LIF --
__global__ __launch_bounds__(64) void k_attn(
    const float* __restrict__ cellmem, const float* __restrict__ attnmem,
    const int* __restrict__ mask, const float* __restrict__ betas,
    float* __restrict__ ob)
{
    const int bh = blockIdx.x;
    const int b = bh >> 3, h = bh & 7, w = b & 63;
    const int n = threadIdx.x;

    __shared__ unsigned kb[64], vb[64];
    __shared__ unsigned long long vT[32];

    kb[n] = g_kbits[bh * 64 + n];
    vb[n] = g_vbits[bh * 64 + n];
    __syncthreads();
    if (n < 32) {
        unsigned long long t = 0ull;
#pragma unroll
        for (int m = 0; m < 64; ++m)
            t |= (unsigned long long)((vb[m] >> n) & 1u) << m;
        vT[n] = t;
    }
    const unsigned q = g_qbits[bh * 64 + n];
    const float b3 = betas[3], b4 = betas[4];

    const float4* bias4 = (const float4*)(g_bias + h * 4096 + n * 64);
    const int4*   mp4   = (const int4*)(mask + w * 4096 + n * 64);
    const float4* cp4   = (const float4*)(cellmem + ((size_t)bh * 64 + n) * 64);
    float4*       cn4   = (float4*)(ob + O_CELL + ((size_t)bh * 64 + n) * 64);

    __syncthreads();

    unsigned long long amask = 0ull;
#pragma unroll 4
    for (int mq = 0; mq < 16; ++mq) {
        float4 bv = bias4[mq];
        int4   mv = mp4[mq];
        float4 cv = cp4[mq];
        float4 co;
        {
            int m = mq * 4 + 0;
            float gate = fmaf((float)__popc(q & kb[m]), 0.125f, bv.x);
            if (mv.x != 0) gate = 0.0f;
            float mem = fmaf(b3, cv.x, gate);
            bool  s   = mem > 1.0f;
            co.x = s ? 0.0f : mem;
            amask |= (unsigned long long)(s ? 1 : 0) << m;
        }
        {
            int m = mq * 4 + 1;
            float gate = fmaf((float)__popc(q & kb[m]), 0.125f, bv.y);
            if (mv.y != 0) gate = 0.0f;
            float mem = fmaf(b3, cv.y, gate);
            bool  s   = mem > 1.0f;
            co.y = s ? 0.0f : mem;
            amask |= (unsigned long long)(s ? 1 : 0) << m;
        }
        {
            int m = mq * 4 + 2;
            float gate = fmaf((float)__popc(q & kb[m]), 0.125f, bv.z);
            if (mv.z != 0) gate = 0.0f;
            float mem = fmaf(b3, cv.z, gate);
            bool  s   = mem > 1.0f;
            co.z = s ? 0.0f : mem;
            amask |= (unsigned long long)(s ? 1 : 0) << m;
        }
        {
            int m = mq * 4 + 3;
            float gate = fmaf((float)__popc(q & kb[m]), 0.125f, bv.w);
            if (mv.w != 0) gate = 0.0f;
            float mem = fmaf(b3, cv.w, gate);
            bool  s   = mem > 1.0f;
            co.w = s ? 0.0f : mem;
            amask |= (unsigned long long)(s ? 1 : 0) << m;
        }
        cn4[mq] = co;
    }

    const size_t arow = ((size_t)b * 64 + n) * 256 + h * 32;
    const float*   ap  = attnmem + arow;
    float*         amp = ob + O_AM + arow;
    __nv_bfloat16* o2  = g_sp + arow;
#pragma unroll 8
    for (int d2 = 0; d2 < 32; ++d2) {
        float o   = (float)__popcll(amask & vT[d2]) * 0.25f;
        float mem = fmaf(b4, ap[d2], o);
        float s   = mem > 0.5f ? 1.0f : 0.0f;
        amp[d2] = mem - 0.5f * s;
        o2[d2]  = __float2bfloat16(s);   // exact 0/1
    }
}

// ---------------- final epilogue: BN(o) + LIF -> out spikes + om ----------------
__global__ void k_out_epi(const float* __restrict__ outmem,
                          const float* __restrict__ betas,
                          float* __restrict__ ob)
{
    const size_t i = (size_t)blockIdx.x * 256 + threadIdx.x;
    const int c = (int)(i & 255);
    float y   = fmaf(g_yo[i], g_scale_o[c], g_shift_o[c]);
    float mem = fmaf(betas[5], outmem[i], y);
    float s   = mem > 1.0f ? 1.0f : 0.0f;
    ob[i]        = s;
    ob[O_OM + i] = mem - s;
}

// ---------------- launch ----------------
extern "C" void kernel_launch(void* const* d_in, const int* in_sizes, int n_in,
                              void* d_out, int out_size)
{
    const float* x       = (const float*)d_in[0];
    const float* qmem    = (const float*)d_in[1];
    const float* kmem    = (const float*)d_in[2];
    const float* vmem    = (const float*)d_in[3];
    const float* cellmem = (const float*)d_in[4];
    const float* attnmem = (const float*)d_in[5];
    const float* outmem  = (const float*)d_in[6];
    const float* Wq  = (const float*)d_in[7];
    const float* gq  = (const float*)d_in[9];
    const float* btq = (const float*)d_in[10];
    const float* Wk  = (const float*)d_in[11];
    const float* gk  = (const float*)d_in[13];
    const float* btk = (const float*)d_in[14];
    const float* Wv  = (const float*)d_in[15];
    const float* gv  = (const float*)d_in[17];
    const float* btv = (const float*)d_in[18];
    const float* Wfb = (const float*)d_in[19];
    const float* bfb = (const float*)d_in[20];
    const float* Wo  = (const float*)d_in[21];
    const float* go  = (const float*)d_in[23];
    const float* bto = (const float*)d_in[24];
    const float* rel_table = (const float*)d_in[25];
    const float* betas     = (const float*)d_in[26];
    const int*   mask      = (const int*)d_in[27];
    const int*   rel_index = (const int*)d_in[28];
    float* ob = (float*)d_out;

    // 2 x 98304 pipeline stages + 1024 alignment slack
    cudaFuncSetAttribute(hgemm, cudaFuncAttributeMaxDynamicSharedMemorySize, 197632);

    k_cs     <<<1024, 512>>>(cellmem);
    k_bias   <<<128, 256>>>(rel_table, rel_index);
    k_split_a<<<16384, 256>>>(x);
    k_split_w<<<256, 256>>>(Wq, Wk, Wv, Wo);

    // QKV GEMM: N-block fast in grid.x for L2 reuse of A across the 6 col-blocks
    dim3 gq3(6, 512);
    hgemm<<<gq3, 256, 197632>>>(0);

    k_stats_final3<<<3, 256>>>(gq, btq, gk, btk, gv, btv);

    k_qkv_epi<<<4096, 256>>>(qmem, kmem, vmem, Wfb, bfb, betas, ob);
    k_attn   <<<8192, 64>>>(cellmem, attnmem, mask, betas, ob);

    dim3 go1(2, 512);
    hgemm<<<go1, 256, 197632>>>(1);
    k_stats_final_o<<<1, 256>>>(go, bto);

    k_out_epi<<<65536, 256>>>(outmem, betas, ob);
}

// round 17
// speedup vs baseline: 1.2280x; 1.0030x over previous
#include <cuda_runtime.h>
#include <cuda_bf16.h>
#include <math.h>

// Problem constants (fixed by setup_inputs):
// B=16, nW=64, BnW=1024, N=64, C=256, H=8, d=32, rows R=65536
static const size_t SEG    = 16777216ull;
static const size_t O_QM   = 1ull * SEG;
static const size_t O_KM   = 2ull * SEG;
static const size_t O_VM   = 3ull * SEG;
static const size_t O_CELL = 4ull * SEG;
static const size_t O_AM   = 6ull * SEG;
static const size_t O_OM   = 7ull * SEG;

// ---------------- static device scratch (no allocations) ----------------
__device__ float          g_y[50331648];     // pre-BN q|k|v activations (65536 x 768)
__device__ float          g_yo[16777216];    // pre-BN o activations (65536 x 256)
__device__ __nv_bfloat16  g_a0[16777216];    // bf16 split planes of x (65536 x 256)
__device__ __nv_bfloat16  g_a1[16777216];
__device__ __nv_bfloat16  g_a2[16777216];
__device__ __nv_bfloat16  g_sp[16777216];    // attn-LIF spikes as bf16 (exact 0/1)
__device__ __nv_bfloat16  g_w0[262144];      // bf16 split planes of [Wq;Wk;Wv;Wo] (1024 x 256)
__device__ __nv_bfloat16  g_w1[262144];
__device__ __nv_bfloat16  g_w2[262144];
__device__ float          g_cs[524288];      // (BnW, N, H) coincidence state
__device__ float          g_bias[32768];     // (H, N, N) relative position bias
__device__ unsigned       g_qbits[524288];   // (BnW, H, N): packed spikes over d=32
__device__ unsigned       g_kbits[524288];
__device__ unsigned       g_vbits[524288];
__device__ float          g_pf[786432];      // stats partials: 512 rowblocks x (768 sum | 768 sumsq)
__device__ float          g_scale[768], g_shift[768];
__device__ float          g_scale_o[256], g_shift_o[256];

// ---------------- warp mma helpers (legacy path, plain sm_103) ----------------
__device__ __forceinline__ unsigned smem_u32(const void* p) {
    return (unsigned)__cvta_generic_to_shared(p);
}
__device__ __forceinline__ void ldsm_x4(unsigned r[4], unsigned saddr) {
    asm volatile("ldmatrix.sync.aligned.m8n8.x4.shared.b16 {%0,%1,%2,%3}, [%4];"
                 : "=r"(r[0]), "=r"(r[1]), "=r"(r[2]), "=r"(r[3]) : "r"(saddr));
}
__device__ __forceinline__ void mma_bf16(float* c, const unsigned* a, const unsigned* b) {
    asm volatile(
        "mma.sync.aligned.m16n8k16.row.col.f32.bf16.bf16.f32 "
        "{%0,%1,%2,%3}, {%4,%5,%6,%7}, {%8,%9}, {%0,%1,%2,%3};"
        : "+f"(c[0]), "+f"(c[1]), "+f"(c[2]), "+f"(c[3])
        : "r"(a[0]), "r"(a[1]), "r"(a[2]), "r"(a[3]), "r"(b[0]), "r"(b[1]));
}
__device__ __forceinline__ void cp16(unsigned dst, const void* src) {
    asm volatile("cp.async.cg.shared.global [%0], [%1], 16;" :: "r"(dst), "l"(src));
}
#define CP_COMMIT() asm volatile("cp.async.commit_group;" ::: "memory")
#define CP_WAIT0()  asm volatile("cp.async.wait_group 0;" ::: "memory")
#define CP_WAIT1()  asm volatile("cp.async.wait_group 1;" ::: "memory")

// ---------------- cs = mean over last axis of cell_mem ----------------
__global__ void k_cs(const float* __restrict__ cell) {
    const int b = blockIdx.x;
    const int t = threadIdx.x;
    const int h = t >> 6, n = t & 63;
    const float4* p = (const float4*)(cell + (((size_t)b * 8 + h) * 64 + n) * 64);
    float s = 0.f;
#pragma unroll
    for (int i = 0; i < 16; ++i) { float4 v = p[i]; s += (v.x + v.y) + (v.z + v.w); }
    g_cs[b * 512 + n * 8 + h] = s * (1.0f / 64.0f);
}

// ---------------- relative-position bias gather ----------------
__global__ void k_bias(const float* __restrict__ rel_table, const int* __restrict__ rel_index) {
    const int i = blockIdx.x * 256 + threadIdx.x;
    const int h = i >> 12, nm = i & 4095;
    g_bias[i] = rel_table[rel_index[nm] * 8 + h];
}

// ---------------- bf16 3-way splits (exact residual decomposition) ----------------
__device__ __forceinline__ void split3(float a, __nv_bfloat16& h0, __nv_bfloat16& h1,
                                       __nv_bfloat16& h2) {
    h0 = __float2bfloat16(a);
    float r1 = a - __bfloat162float(h0);
    h1 = __float2bfloat16(r1);
    float r2 = r1 - __bfloat162float(h1);
    h2 = __float2bfloat16(r2);
}
__global__ void k_split_a(const float* __restrict__ x) {
    const size_t i = ((size_t)blockIdx.x * 256 + threadIdx.x) * 4;
    float4 v = *(const float4*)(x + i);
    __nv_bfloat16 p0[4], p1[4], p2[4];
    split3(v.x, p0[0], p1[0], p2[0]);
    split3(v.y, p0[1], p1[1], p2[1]);
    split3(v.z, p0[2], p1[2], p2[2]);
    split3(v.w, p0[3], p1[3], p2[3]);
    *(uint2*)(g_a0 + i) = *(uint2*)p0;
    *(uint2*)(g_a1 + i) = *(uint2*)p1;
    *(uint2*)(g_a2 + i) = *(uint2*)p2;
}
__global__ void k_split_w(const float* __restrict__ Wq, const float* __restrict__ Wk,
                          const float* __restrict__ Wv, const float* __restrict__ Wo) {
    const size_t i = ((size_t)blockIdx.x * 256 + threadIdx.x) * 4;  // < 262144
    const int row = (int)(i >> 8);
    const float* src = (row < 256) ? Wq : (row < 512) ? Wk : (row < 768) ? Wv : Wo;
    float4 v = *(const float4*)(src + ((size_t)(row & 255) * 256 + (i & 255)));
    __nv_bfloat16 p0[4], p1[4], p2[4];
    split3(v.x, p0[0], p1[0], p2[0]);
    split3(v.y, p0[1], p1[1], p2[1]);
    split3(v.z, p0[2], p1[2], p2[2]);
    split3(v.w, p0[3], p1[3], p2[3]);
    *(uint2*)(g_w0 + i) = *(uint2*)p0;
    *(uint2*)(g_w1 + i) = *(uint2*)p1;
    *(uint2*)(g_w2 + i) = *(uint2*)p2;
}

// ---------------- HMMA GEMM: Y[m, colOff+c] = sum_k A[m,k]*W[c,k], K=256 --------
// 3-way bf16 split, fp32 mma accumulate; pairs (ia,ib) with ia+ib<=2.
// Block tile 128x128, *16 warps* (512 thr, warp grid 4m x 4n, 32x32/warp) for
// 2x warp supply per SMSP at unchanged smem; cp.async DOUBLE-BUFFERED K64 chunks.
// Per-output mma order identical to R15 -> outputs bitwise identical.
// Fused BN column stats (sum/sumsq) -> g_pf[rowblock=blockIdx.y].
// mode 0 (QKV): A = g_a0/1/2, B rows/colOff = blockIdx.x*128 (768 cols), Y=g_y.
// mode 1 (O):   A = g_sp (exact 0/1, 3 pairs), B rows 768+bx*128, Y=g_yo (256 cols).
__global__ __launch_bounds__(512) void hgemm(int mode)
{
    extern __shared__ unsigned char smem_raw[];
    const unsigned rawaddr = smem_u32(smem_raw);
    const unsigned pad = (1024u - (rawaddr & 1023u)) & 1023u;
    unsigned char* smem = smem_raw + pad;
    const unsigned sbase = rawaddr + pad;

    const int tid  = threadIdx.x;
    const int lane = tid & 31, wid = tid >> 5;
    const int wm = wid & 3, wn = wid >> 2;   // warp grid 4(m) x 4(n)
    const int m0 = blockIdx.y << 7;
    const int nApl   = mode ? 1 : 3;
    const int brow0  = mode ? (768 + (blockIdx.x << 7)) : (blockIdx.x << 7);
    const int colOff = blockIdx.x << 7;
    float* Y  = mode ? g_yo : g_y;
    const int ldY = mode ? 256 : 768;

    const __nv_bfloat16* APl[3];
    if (mode) { APl[0] = g_sp; APl[1] = g_sp; APl[2] = g_sp; }
    else      { APl[0] = g_a0; APl[1] = g_a1; APl[2] = g_a2; }
    const __nv_bfloat16* BPl[3] = { g_w0, g_w1, g_w2 };

    const unsigned STG = 98304u;                    // bytes per pipeline stage
    const unsigned offA[3] = { 0u, 16384u, 32768u };
    const unsigned offB[3] = { 49152u, 65536u, 81920u };

    // cp.async staging of one K64 chunk into stage st (512 threads)
    auto stage_chunk = [&](int kc, int st) {
        const int k0 = kc * 64;
        const unsigned base = sbase + (unsigned)st * STG;
        for (int p = 0; p < nApl; ++p) {
            const __nv_bfloat16* src = APl[p] + (size_t)m0 * 256 + k0;
#pragma unroll
            for (int it = 0; it < 2; ++it) {
                const int idx = tid + it * 512;        // 0..1023
                const int row = idx >> 3, ch = idx & 7;
                cp16(base + offA[p] + row * 128 + ((ch ^ (row & 7)) << 4),
                     src + (size_t)row * 256 + ch * 8);
            }
        }
#pragma unroll
        for (int p = 0; p < 3; ++p) {
            const __nv_bfloat16* src = BPl[p] + (size_t)brow0 * 256 + k0;
#pragma unroll
            for (int it = 0; it < 2; ++it) {
                const int idx = tid + it * 512;
                const int row = idx >> 3, ch = idx & 7;
                cp16(base + offB[p] + row * 128 + ((ch ^ (row & 7)) << 4),
                     src + (size_t)row * 256 + ch * 8);
            }
        }
    };

    // ldmatrix lane geometry (canonical m16n8k16 fragment orders)
    const int a_m  = lane & 15;            // row within 16
    const int a_kh = lane >> 4;            // k-half select 0/1
    const int b_n  = (lane & 7) | ((lane & 16) >> 1);  // n row within 16
    const int b_kh = (lane >> 3) & 1;
    int arow[2], brow[2];
#pragma unroll
    for (int mt = 0; mt < 2; ++mt) arow[mt] = wm * 32 + mt * 16 + a_m;
#pragma unroll
    for (int np = 0; np < 2; ++np) brow[np] = wn * 32 + np * 16 + b_n;

    float acc[2][4][4];
#pragma unroll
    for (int mt = 0; mt < 2; ++mt)
#pragma unroll
        for (int nt = 0; nt < 4; ++nt)
#pragma unroll
            for (int j = 0; j < 4; ++j) acc[mt][nt][j] = 0.f;

    stage_chunk(0, 0);
    CP_COMMIT();

    int st = 0;
    for (int kc = 0; kc < 4; ++kc) {
        if (kc < 3) { stage_chunk(kc + 1, st ^ 1); CP_COMMIT(); CP_WAIT1(); }
        else        { CP_WAIT0(); }
        __syncthreads();

        const unsigned base = sbase + (unsigned)st * STG;
#pragma unroll
        for (int ks = 0; ks < 4; ++ks) {
            unsigned af[3][2][4];
#pragma unroll
            for (int ia = 0; ia < 3; ++ia) {
                if (ia >= nApl) break;
#pragma unroll
                for (int mt = 0; mt < 2; ++mt) {
                    const unsigned chunk = (unsigned)(ks * 2 + a_kh);
                    ldsm_x4(af[ia][mt], base + offA[ia] + arow[mt] * 128 +
                                        ((chunk ^ (arow[mt] & 7)) << 4));
                }
            }
#pragma unroll
            for (int ib = 0; ib < 3; ++ib) {
                unsigned bf[2][4];   // np -> {b0,b1 of nt=2np, b0,b1 of nt=2np+1}
#pragma unroll
                for (int np = 0; np < 2; ++np) {
                    const unsigned chunk = (unsigned)(ks * 2 + b_kh);
                    ldsm_x4(bf[np], base + offB[ib] + brow[np] * 128 +
                                    ((chunk ^ (brow[np] & 7)) << 4));
                }
                // pairs with ia+ib <= 2 (R13 scheme)
                const int iamax = (nApl < 3 - ib) ? nApl : (3 - ib);
                for (int ia = 0; ia < iamax; ++ia)
#pragma unroll
                    for (int mt = 0; mt < 2; ++mt)
#pragma unroll
                        for (int nt = 0; nt < 4; ++nt)
                            mma_bf16(acc[mt][nt], af[ia][mt], &bf[nt >> 1][(nt & 1) * 2]);
            }
        }
        __syncthreads();           // all warps done with stage st before reuse
        st ^= 1;
    }

    // ---- store tile (c0,c1 -> row l/4; c2,c3 -> row l/4+8) ----
    const int lrow = lane >> 2, lcp = (lane & 3) * 2;
#pragma unroll
    for (int mt = 0; mt < 2; ++mt) {
        const int row = m0 + wm * 32 + mt * 16 + lrow;
        float* yr  = Y + (size_t)row * ldY + colOff + wn * 32;
        float* yr2 = yr + 8 * (size_t)ldY;
#pragma unroll
        for (int nt = 0; nt < 4; ++nt) {
            *(float2*)(yr  + nt * 8 + lcp) = make_float2(acc[mt][nt][0], acc[mt][nt][1]);
            *(float2*)(yr2 + nt * 8 + lcp) = make_float2(acc[mt][nt][2], acc[mt][nt][3]);
        }
    }

    // ---- fused BN column stats: per-lane partial, shfl tree, smem reduce ----
    float cs[4][2], cq[4][2];
#pragma unroll
    for (int nt = 0; nt < 4; ++nt) {
        cs[nt][0] = (acc[0][nt][0] + acc[0][nt][2]) + (acc[1][nt][0] + acc[1][nt][2]);
        cs[nt][1] = (acc[0][nt][1] + acc[0][nt][3]) + (acc[1][nt][1] + acc[1][nt][3]);
        float q0 = acc[0][nt][0] * acc[0][nt][0];
        q0 = fmaf(acc[0][nt][2], acc[0][nt][2], q0);
        q0 = fmaf(acc[1][nt][0], acc[1][nt][0], q0);
        q0 = fmaf(acc[1][nt][2], acc[1][nt][2], q0);
        cq[nt][0] = q0;
        float q1 = acc[0][nt][1] * acc[0][nt][1];
        q1 = fmaf(acc[0][nt][3], acc[0][nt][3], q1);
        q1 = fmaf(acc[1][nt][1], acc[1][nt][1], q1);
        q1 = fmaf(acc[1][nt][3], acc[1][nt][3], q1);
        cq[nt][1] = q1;
    }
#pragma unroll
    for (int off = 4; off < 32; off <<= 1)
#pragma unroll
        for (int nt = 0; nt < 4; ++nt) {
            cs[nt][0] += __shfl_xor_sync(0xffffffffu, cs[nt][0], off);
            cs[nt][1] += __shfl_xor_sync(0xffffffffu, cs[nt][1], off);
            cq[nt][0] += __shfl_xor_sync(0xffffffffu, cq[nt][0], off);
            cq[nt][1] += __shfl_xor_sync(0xffffffffu, cq[nt][1], off);
        }
    __syncthreads();                         // smem tiles no longer needed
    float* redS = (float*)smem;              // [4][128]
    float* redQ = redS + 512;                // [4][128]
    if (lane < 4) {
#pragma unroll
        for (int nt = 0; nt < 4; ++nt) {
            const int col = wn * 32 + nt * 8 + lane * 2;
            redS[wm * 128 + col]     = cs[nt][0];
            redS[wm * 128 + col + 1] = cs[nt][1];
            redQ[wm * 128 + col]     = cq[nt][0];
            redQ[wm * 128 + col + 1] = cq[nt][1];
        }
    }
    __syncthreads();
    if (tid < 128) {
        float s = (redS[tid] + redS[128 + tid]) + (redS[256 + tid] + redS[384 + tid]);
        float q = (redQ[tid] + redQ[128 + tid]) + (redQ[256 + tid] + redQ[384 + tid]);
        g_pf[(size_t)blockIdx.y * 1536 + colOff + tid]       = s;
        g_pf[(size_t)blockIdx.y * 1536 + 768 + colOff + tid] = q;
    }
}

// ---------------- BN stats finalize: Kahan-fp32 over 512 partials ----------------
__global__ void k_stats_final3(const float* __restrict__ g0, const float* __restrict__ b0,
                               const float* __restrict__ g1, const float* __restrict__ b1,
                               const float* __restrict__ g2, const float* __restrict__ b2) {
    const int grp = blockIdx.x;
    const float* gamma = (grp == 0) ? g0 : (grp == 1) ? g1 : g2;
    const float* beta  = (grp == 0) ? b0 : (grp == 1) ? b1 : b2;
    const int colOff = grp << 8;
    const int c = colOff + threadIdx.x;
    float s = 0.f, cs = 0.f, q = 0.f, cq = 0.f;
    for (int b = 0; b < 512; ++b) {
        float v  = g_pf[(size_t)b * 1536 + c];
        float y  = v - cs; float t  = s + y;  cs = (t - s) - y;  s = t;
        float w  = g_pf[(size_t)b * 1536 + 768 + c];
        float y2 = w - cq; float t2 = q + y2; cq = (t2 - q) - y2; q = t2;
    }
    const double mean = (double)s * (1.0 / 65536.0);
    const double var  = (double)q * (1.0 / 65536.0) - mean * mean;
    const double rs   = 1.0 / sqrt(var + 1e-5);
    const double g    = (double)gamma[threadIdx.x];
    g_scale[c] = (float)(g * rs);
    g_shift[c] = (float)((double)beta[threadIdx.x] - g * rs * mean);
}
__global__ void k_stats_final_o(const float* __restrict__ gamma, const float* __restrict__ beta) {
    const int c = threadIdx.x;
    float s = 0.f, cs = 0.f, q = 0.f, cq = 0.f;
    for (int b = 0; b < 512; ++b) {
        float v  = g_pf[(size_t)b * 1536 + c];
        float y  = v - cs; float t  = s + y;  cs = (t - s) - y;  s = t;
        float w  = g_pf[(size_t)b * 1536 + 768 + c];
        float y2 = w - cq; float t2 = q + y2; cq = (t2 - q) - y2; q = t2;
    }
    const double mean = (double)s * (1.0 / 65536.0);
    const double var  = (double)q * (1.0 / 65536.0) - mean * mean;
    const double rs   = 1.0 / sqrt(var + 1e-5);
    const double g    = (double)gamma[c];
    g_scale_o[c] = (float)(g * rs);
    g_shift_o[c] = (float)((double)beta[c] - g * rs * mean);
}

// ---------------- Q/K/V epilogue: BN + feedback + LIF + bit-pack ----------------
__global__ __launch_bounds__(256) void k_qkv_epi(
    const float* __restrict__ qmem, const float* __restrict__ kmem,
    const float* __restrict__ vmem,
    const float* __restrict__ Wfb, const float* __restrict__ bfb,
    const float* __restrict__ betas, float* __restrict__ ob)
{
    const int c    = threadIdx.x;
    const int lane = c & 31;
    const int h    = c >> 5;
    float wf[8];
#pragma unroll
    for (int j = 0; j < 8; ++j) wf[j] = Wfb[c * 8 + j];
    const float bfbc = bfb[c];
    const float b0 = betas[0], b1 = betas[1], b2 = betas[2];
    const float sq = g_scale[c],       hq = g_shift[c];
    const float sk = g_scale[256 + c], hk = g_shift[256 + c];
    const float sv = g_scale[512 + c], hv = g_shift[512 + c];

    const int r0 = blockIdx.x * 16;
    for (int rr = 0; rr < 16; ++rr) {
        const int r = r0 + rr;
        const int b = r >> 6, n = r & 63;
        const float* csp = g_cs + b * 512 + n * 8;
        float fb = bfbc;
#pragma unroll
        for (int j = 0; j < 8; ++j) fb = fmaf(csp[j], wf[j], fb);

        const size_t yo = (size_t)r * 768 + c;
        const size_t mo = (size_t)r * 256 + c;
        const int bitidx = (b * 8 + h) * 64 + n;
        {
            float pre = fmaf(g_y[yo], sq, hq) + fb;
            float mem = fmaf(b0, qmem[mo], pre);
            bool  s   = mem > 1.0f;
            ob[O_QM + mo] = s ? (mem - 1.0f) : mem;
            unsigned bits = __ballot_sync(0xffffffffu, s);
            if (lane == 0) g_qbits[bitidx] = bits;
        }
        {
            float pre = fmaf(g_y[yo + 256], sk, hk) + fb;
            float mem = fmaf(b1, kmem[mo], pre);
            bool  s   = mem > 1.0f;
            ob[O_KM + mo] = s ? (mem - 1.0f) : mem;
            unsigned bits = __ballot_sync(0xffffffffu, s);
            if (lane == 0) g_kbits[bitidx] = bits;
        }
        {
            float pre = fmaf(g_y[yo + 512], sv, hv) + fb;
            float mem = fmaf(b2, vmem[mo], pre);
            bool  s   = mem > 1.0f;
            ob[O_VM + mo] = s ? (mem - 1.0f) : mem;
            unsigned bits = __ballot_sync(0xffffffffu, s);
            if (lane == 0) g_vbits[bitidx] = bits;
        }
    }
}

// ---------------- attention: gate -> cell LIF (zero reset) -> attn@v -> attn LIF --
__global__ __launch_bounds__(64) void k_attn(
    const float* __restrict__ cellmem, const float* __restrict__ attnmem,
    const int* __restrict__ mask, const float* __restrict__ betas,
    float* __restrict__ ob)
{
    const int bh = blockIdx.x;
    const int b = bh >> 3, h = bh & 7, w = b & 63;
    const int n = threadIdx.x;

    __shared__ unsigned kb[64], vb[64];
    __shared__ unsigned long long vT[32];

    kb[n] = g_kbits[bh * 64 + n];
    vb[n] = g_vbits[bh * 64 + n];
    __syncthreads();
    if (n < 32) {
        unsigned long long t = 0ull;
#pragma unroll
        for (int m = 0; m < 64; ++m)
            t |= (unsigned long long)((vb[m] >> n) & 1u) << m;
        vT[n] = t;
    }
    const unsigned q = g_qbits[bh * 64 + n];
    const float b3 = betas[3], b4 = betas[4];

    const float4* bias4 = (const float4*)(g_bias + h * 4096 + n * 64);
    const int4*   mp4   = (const int4*)(mask + w * 4096 + n * 64);
    const float4* cp4   = (const float4*)(cellmem + ((size_t)bh * 64 + n) * 64);
    float4*       cn4   = (float4*)(ob + O_CELL + ((size_t)bh * 64 + n) * 64);

    __syncthreads();

    unsigned long long amask = 0ull;
#pragma unroll 4
    for (int mq = 0; mq < 16; ++mq) {
        float4 bv = bias4[mq];
        int4   mv = mp4[mq];
        float4 cv = cp4[mq];
        float4 co;
        {
            int m = mq * 4 + 0;
            float gate = fmaf((float)__popc(q & kb[m]), 0.125f, bv.x);
            if (mv.x != 0) gate = 0.0f;
            float mem = fmaf(b3, cv.x, gate);
            bool  s   = mem > 1.0f;
            co.x = s ? 0.0f : mem;
            amask |= (unsigned long long)(s ? 1 : 0) << m;
        }
        {
            int m = mq * 4 + 1;
            float gate = fmaf((float)__popc(q & kb[m]), 0.125f, bv.y);
            if (mv.y != 0) gate = 0.0f;
            float mem = fmaf(b3, cv.y, gate);
            bool  s   = mem > 1.0f;
            co.y = s ? 0.0f : mem;
            amask |= (unsigned long long)(s ? 1 : 0) << m;
        }
        {
            int m = mq * 4 + 2;
            float gate = fmaf((float)__popc(q & kb[m]), 0.125f, bv.z);
            if (mv.z != 0) gate = 0.0f;
            float mem = fmaf(b3, cv.z, gate);
            bool  s   = mem > 1.0f;
            co.z = s ? 0.0f : mem;
            amask |= (unsigned long long)(s ? 1 : 0) << m;
        }
        {
            int m = mq * 4 + 3;
            float gate = fmaf((float)__popc(q & kb[m]), 0.125f, bv.w);
            if (mv.w != 0) gate = 0.0f;
            float mem = fmaf(b3, cv.w, gate);
            bool  s   = mem > 1.0f;
            co.w = s ? 0.0f : mem;
            amask |= (unsigned long long)(s ? 1 : 0) << m;
        }
        cn4[mq] = co;
    }

    const size_t arow = ((size_t)b * 64 + n) * 256 + h * 32;
    const float*   ap  = attnmem + arow;
    float*         amp = ob + O_AM + arow;
    __nv_bfloat16* o2  = g_sp + arow;
#pragma unroll 8
    for (int d2 = 0; d2 < 32; ++d2) {
        float o   = (float)__popcll(amask & vT[d2]) * 0.25f;
        float mem = fmaf(b4, ap[d2], o);
        float s   = mem > 0.5f ? 1.0f : 0.0f;
        amp[d2] = mem - 0.5f * s;
        o2[d2]  = __float2bfloat16(s);   // exact 0/1
    }
}

// ---------------- final epilogue: BN(o) + LIF -> out spikes + om ----------------
__global__ void k_out_epi(const float* __restrict__ outmem,
                          const float* __restrict__ betas,
                          float* __restrict__ ob)
{
    const size_t i = (size_t)blockIdx.x * 256 + threadIdx.x;
    const int c = (int)(i & 255);
    float y   = fmaf(g_yo[i], g_scale_o[c], g_shift_o[c]);
    float mem = fmaf(betas[5], outmem[i], y);
    float s   = mem > 1.0f ? 1.0f : 0.0f;
    ob[i]        = s;
    ob[O_OM + i] = mem - s;
}

// ---------------- launch ----------------
extern "C" void kernel_launch(void* const* d_in, const int* in_sizes, int n_in,
                              void* d_out, int out_size)
{
    const float* x       = (const float*)d_in[0];
    const float* qmem    = (const float*)d_in[1];
    const float* kmem    = (const float*)d_in[2];
    const float* vmem    = (const float*)d_in[3];
    const float* cellmem = (const float*)d_in[4];
    const float* attnmem = (const float*)d_in[5];
    const float* outmem  = (const float*)d_in[6];
    const float* Wq  = (const float*)d_in[7];
    const float* gq  = (const float*)d_in[9];
    const float* btq = (const float*)d_in[10];
    const float* Wk  = (const float*)d_in[11];
    const float* gk  = (const float*)d_in[13];
    const float* btk = (const float*)d_in[14];
    const float* Wv  = (const float*)d_in[15];
    const float* gv  = (const float*)d_in[17];
    const float* btv = (const float*)d_in[18];
    const float* Wfb = (const float*)d_in[19];
    const float* bfb = (const float*)d_in[20];
    const float* Wo  = (const float*)d_in[21];
    const float* go  = (const float*)d_in[23];
    const float* bto = (const float*)d_in[24];
    const float* rel_table = (const float*)d_in[25];
    const float* betas     = (const float*)d_in[26];
    const int*   mask      = (const int*)d_in[27];
    const int*   rel_index = (const int*)d_in[28];
    float* ob = (float*)d_out;

    // 2 x 98304 pipeline stages + 1024 alignment slack
    cudaFuncSetAttribute(hgemm, cudaFuncAttributeMaxDynamicSharedMemorySize, 197632);

    k_cs     <<<1024, 512>>>(cellmem);
    k_bias   <<<128, 256>>>(rel_table, rel_index);
    k_split_a<<<16384, 256>>>(x);
    k_split_w<<<256, 256>>>(Wq, Wk, Wv, Wo);

    // QKV GEMM: N-block fast in grid.x for L2 reuse of A across the 6 col-blocks
    dim3 gq3(6, 512);
    hgemm<<<gq3, 512, 197632>>>(0);

    k_stats_final3<<<3, 256>>>(gq, btq, gk, btk, gv, btv);

    k_qkv_epi<<<4096, 256>>>(qmem, kmem, vmem, Wfb, bfb, betas, ob);
    k_attn   <<<8192, 64>>>(cellmem, attnmem, mask, betas, ob);

    dim3 go1(2, 512);
    hgemm<<<go1, 512, 197632>>>(1);
    k_stats_final_o<<<1, 256>>>(go, bto);

    k_out_epi<<<65536, 256>>>(outmem, betas, ob);
}